// round 1
// baseline (speedup 1.0000x reference)
#include <cuda_runtime.h>
#include <math.h>

#define TT 32768
#define BB 64
#define SS 512
#define HH 768
#define CC 50
#define MM 2000
#define TW 1024          /* TT/32 */
#define NK 128           /* split-K chunks for final gemm */
#define KCH (TT/NK)      /* 256 tokens per chunk */
#define CP 52            /* C padded to multiple of 4 */

// ---------------- scratch (static device memory; no allocations) ----------------
__device__ float g_e_nts[TT], g_vn[TT], g_e_mts[TT], g_vm[TT], g_e_uts[TT], g_vc[TT];
__device__ float g_den_m[MM], g_mscore[MM], g_coef[MM];
__device__ unsigned g_mbit[MM * TW];            // 8 MB mention-activity bitmask
__device__ float g_cmax[CC], g_cden[CC];
__device__ int   g_hasmen[CC];
__device__ float g_den_nb[CC * BB], g_nsc[CC * BB], g_q[CC * BB];
__device__ float g_invu[CC];
__device__ int   g_hasutt[CC];
__device__ float g_gsum[(size_t)CC * TT];       // 6.5 MB: per-char mention token weights / e_mts
__device__ float g_scorep[CC * 8 * 3];
__device__ float g_attn[CC * 4];
__device__ float g_WT[(size_t)TT * CP];         // 6.8 MB: transposed combined weights [T, Cpad]
__device__ float g_partial[(size_t)NK * CC * HH]; // 19.7 MB split-K partials

// ---------------- helpers ----------------
__device__ __forceinline__ float warpSum(float v) {
#pragma unroll
    for (int o = 16; o; o >>= 1) v += __shfl_down_sync(0xffffffffu, v, o);
    return v;
}
__device__ __forceinline__ float warpMax(float v) {
#pragma unroll
    for (int o = 16; o; o >>= 1) v = fmaxf(v, __shfl_down_sync(0xffffffffu, v, o));
    return v;
}
// valid in thread 0 only; sb must hold >= blockDim/32 floats
__device__ __forceinline__ float blockReduceSum(float v, float* sb) {
    __syncthreads();
    int lane = threadIdx.x & 31, w = threadIdx.x >> 5;
    v = warpSum(v);
    if (lane == 0) sb[w] = v;
    __syncthreads();
    float r = 0.f;
    if (w == 0) {
        int nw = blockDim.x >> 5;
        r = (lane < nw) ? sb[lane] : 0.f;
        r = warpSum(r);
    }
    return r;
}
__device__ __forceinline__ float blockReduceMax(float v, float* sb) {
    __syncthreads();
    int lane = threadIdx.x & 31, w = threadIdx.x >> 5;
    v = warpMax(v);
    if (lane == 0) sb[w] = v;
    __syncthreads();
    float r = -INFINITY;
    if (w == 0) {
        int nw = blockDim.x >> 5;
        r = (lane < nw) ? sb[lane] : -INFINITY;
        r = warpMax(r);
    }
    return r;
}

__device__ __forceinline__ unsigned long long fma2(unsigned long long a,
                                                   unsigned long long b,
                                                   unsigned long long c) {
    unsigned long long d;
    asm("fma.rn.f32x2 %0, %1, %2, %3;" : "=l"(d) : "l"(a), "l"(b), "l"(c));
    return d;
}

// ---------------- K1: per-token scalar projections (one pass over story) ----------------
__global__ void k_token(const float* __restrict__ se,
                        const float* __restrict__ wnt, const float* __restrict__ bnt,
                        const float* __restrict__ wn,  const float* __restrict__ bn,
                        const float* __restrict__ wmt, const float* __restrict__ bmt,
                        const float* __restrict__ wm,  const float* __restrict__ bm,
                        const float* __restrict__ wu,  const float* __restrict__ bu,
                        const float* __restrict__ wc,  const float* __restrict__ bc) {
    int gw = (blockIdx.x * blockDim.x + threadIdx.x) >> 5;   // one warp per token
    int lane = threadIdx.x & 31;
    if (gw >= TT) return;
    const float4* row = reinterpret_cast<const float4*>(se) + (size_t)gw * (HH / 4);
    const float4* W0 = reinterpret_cast<const float4*>(wnt);
    const float4* W1 = reinterpret_cast<const float4*>(wn);
    const float4* W2 = reinterpret_cast<const float4*>(wmt);
    const float4* W3 = reinterpret_cast<const float4*>(wm);
    const float4* W4 = reinterpret_cast<const float4*>(wu);
    const float4* W5 = reinterpret_cast<const float4*>(wc);
    float a0 = 0.f, a1 = 0.f, a2 = 0.f, a3 = 0.f, a4 = 0.f, a5 = 0.f;
#pragma unroll
    for (int i = 0; i < (HH / 4) / 32; i++) {
        int j = i * 32 + lane;
        float4 v = row[j];
        float4 w;
        w = W0[j]; a0 += v.x * w.x + v.y * w.y + v.z * w.z + v.w * w.w;
        w = W1[j]; a1 += v.x * w.x + v.y * w.y + v.z * w.z + v.w * w.w;
        w = W2[j]; a2 += v.x * w.x + v.y * w.y + v.z * w.z + v.w * w.w;
        w = W3[j]; a3 += v.x * w.x + v.y * w.y + v.z * w.z + v.w * w.w;
        w = W4[j]; a4 += v.x * w.x + v.y * w.y + v.z * w.z + v.w * w.w;
        w = W5[j]; a5 += v.x * w.x + v.y * w.y + v.z * w.z + v.w * w.w;
    }
    a0 = warpSum(a0); a1 = warpSum(a1); a2 = warpSum(a2);
    a3 = warpSum(a3); a4 = warpSum(a4); a5 = warpSum(a5);
    if (lane == 0) {
        g_e_nts[gw] = expf(a0 + *bnt);
        g_vn[gw]    = a1 + *bn;
        g_e_mts[gw] = expf(a2 + *bmt);
        g_vm[gw]    = a3 + *bm;
        g_e_uts[gw] = expf(a4 + *bu);
        g_vc[gw]    = a5 + *bc;
    }
}

// ---------------- K2: mention pass 1 (single read of 262MB mask; build bitmask) ----------------
__global__ void k_m1(const float* __restrict__ mmask, const float* __restrict__ bmen) {
    int m = blockIdx.x;
    const float* row = mmask + (size_t)m * TT;
    float den = 0.f, num = 0.f;
    for (int t = threadIdx.x; t < TT; t += 256) {
        bool act = (row[t] == 0.f);
        unsigned bal = __ballot_sync(0xffffffffu, act);
        if ((threadIdx.x & 31) == 0) g_mbit[(size_t)m * TW + (t >> 5)] = bal;
        if (act) { float e = g_e_mts[t]; den += e; num = fmaf(e, g_vm[t], num); }
    }
    __shared__ float sb[8];
    float d = blockReduceSum(den, sb);
    float n = blockReduceSum(num, sb);
    if (threadIdx.x == 0) {
        g_den_m[m]  = d;                 // every mention has >=1 active token
        g_mscore[m] = n / d + *bmen;
    }
}

// ---------------- K3: per-character segment softmax stats over mentions ----------------
__global__ void k_seg(const int* __restrict__ seg) {
    int c = blockIdx.x;
    float mx = -INFINITY; int cnt = 0;
    for (int m = threadIdx.x; m < MM; m += 256)
        if (seg[m] == c) { mx = fmaxf(mx, g_mscore[m]); cnt++; }
    __shared__ float sb[8];
    __shared__ float bmx_s;
    float bmx = blockReduceMax(mx, sb);
    if (threadIdx.x == 0) bmx_s = bmx;
    float bcnt = blockReduceSum((float)cnt, sb);   // syncs; makes bmx_s visible
    if (threadIdx.x == 0) g_hasmen[c] = (bcnt > 0.5f) ? 1 : 0;
    __syncthreads();
    float m2 = bmx_s;
    float sum = 0.f;
    for (int m = threadIdx.x; m < MM; m += 256)
        if (seg[m] == c) sum += expf(g_mscore[m] - m2);
    float bsum = blockReduceSum(sum, sb);
    if (threadIdx.x == 0) { g_cmax[c] = m2; g_cden[c] = bsum; }
}

__global__ void k_coef(const int* __restrict__ seg) {
    int m = blockIdx.x * 256 + threadIdx.x;
    if (m < MM) {
        int c = seg[m];
        // coef = (segment softmax weight) / den_m
        g_coef[m] = expf(g_mscore[m] - g_cmax[c]) / (g_cden[c] * g_den_m[m]);
    }
}

// ---------------- K4: gsum[c,t] = sum over c's mentions of coef_m * active(m,t) ----------------
__global__ void k_gsum(const int* __restrict__ seg) {
    int c = blockIdx.x;
    int wbase = blockIdx.y * 128 + threadIdx.x;   // word index into [0, TW)
    __shared__ int sseg[MM];
    for (int i = threadIdx.x; i < MM; i += 128) sseg[i] = seg[i];
    __syncthreads();
    float s[32];
#pragma unroll
    for (int b = 0; b < 32; b++) s[b] = 0.f;
    for (int m = 0; m < MM; m++) {
        if (sseg[m] != c) continue;
        unsigned w = g_mbit[(size_t)m * TW + wbase];
        if (!w) continue;
        float cf = g_coef[m];
#pragma unroll
        for (int b = 0; b < 32; b++)
            if ((w >> b) & 1u) s[b] += cf;
    }
    float* dst = g_gsum + (size_t)c * TT + (size_t)wbase * 32;
#pragma unroll
    for (int b = 0; b < 32; b++) dst[b] = s[b];
}

// ---------------- K5: utterance denominators ----------------
__global__ void k_utt(const float* __restrict__ umask) {
    int c = blockIdx.x;
    const float* row = umask + (size_t)c * TT;
    float du = 0.f;
    for (int t = threadIdx.x; t < TT; t += 256)
        if (row[t] == 0.f) du += g_e_uts[t];
    __shared__ float sb[8];
    float d = blockReduceSum(du, sb);
    if (threadIdx.x == 0) {
        g_hasutt[c] = (d > 0.f) ? 1 : 0;
        g_invu[c]   = (d > 0.f) ? 1.f / d : 0.f;   // nan_to_num path -> 0 weights
    }
}

// ---------------- K6: name per-(c,b) denominators and scores ----------------
__global__ void k_names1(const float* __restrict__ nmask, const float* __restrict__ bname) {
    int c = blockIdx.x;
    int w = threadIdx.x >> 5, lane = threadIdx.x & 31;
    for (int b = w; b < BB; b += 8) {
        float den = 0.f, num = 0.f;
        for (int s = lane; s < SS; s += 32) {
            if (nmask[c * SS + s] == 0.f) {
                float e = g_e_nts[b * SS + s];
                den += e;
                num = fmaf(e, g_vn[b * SS + s], num);
            }
        }
        den = warpSum(den); num = warpSum(num);
        if (lane == 0) {
            g_den_nb[c * BB + b] = den;              // >0: every char has a name token
            g_nsc[c * BB + b]    = num / den + *bname;
        }
    }
}

// ---------------- K7: softmax over blocks -> q[c,b] = p[c,b]/den_nb[c,b] ----------------
__global__ void k_names2() {
    int c = blockIdx.x, b = threadIdx.x;
    __shared__ float sv[BB];
    __shared__ float se2[BB];
    float v = g_nsc[c * BB + b];
    sv[b] = v; __syncthreads();
    float mx = -INFINITY;
#pragma unroll
    for (int i = 0; i < BB; i++) mx = fmaxf(mx, sv[i]);
    float e = expf(v - mx);
    se2[b] = e; __syncthreads();
    float sum = 0.f;
#pragma unroll
    for (int i = 0; i < BB; i++) sum += se2[i];
    g_q[c * BB + b] = (e / sum) / g_den_nb[c * BB + b];
}

// ---------------- K8: combine scores s_k[c] = sum_t w_k[c,t] * vc[t] (split into 8 chunks) ----------------
__global__ void k_scores(const float* __restrict__ nmask, const float* __restrict__ umask) {
    int c = blockIdx.x, ch = blockIdx.y;
    int t0 = ch * (TT / 8);
    float invu = g_invu[c];
    float s0 = 0.f, s1 = 0.f, s2 = 0.f;
    for (int t = t0 + threadIdx.x; t < t0 + TT / 8; t += 256) {
        float vcv = g_vc[t];
        int b = t >> 9, s = t & (SS - 1);
        float wN = (nmask[c * SS + s] == 0.f) ? g_q[c * BB + b] * g_e_nts[t] : 0.f;
        float wM = g_gsum[(size_t)c * TT + t] * g_e_mts[t];
        float wU = (umask[(size_t)c * TT + t] == 0.f) ? g_e_uts[t] * invu : 0.f;
        s0 = fmaf(wN, vcv, s0);
        s1 = fmaf(wM, vcv, s1);
        s2 = fmaf(wU, vcv, s2);
    }
    __shared__ float sb[8];
    float r0 = blockReduceSum(s0, sb);
    float r1 = blockReduceSum(s1, sb);
    float r2 = blockReduceSum(s2, sb);
    if (threadIdx.x == 0) {
        g_scorep[(c * 8 + ch) * 3 + 0] = r0;
        g_scorep[(c * 8 + ch) * 3 + 1] = r1;
        g_scorep[(c * 8 + ch) * 3 + 2] = r2;
    }
}

// ---------------- K9: 3-way combine softmax with availability masks ----------------
__global__ void k_attn(const float* __restrict__ bcomb) {
    int c = threadIdx.x;
    if (c >= CC) return;
    float s0 = 0.f, s1 = 0.f, s2 = 0.f;
#pragma unroll
    for (int k = 0; k < 8; k++) {
        s0 += g_scorep[(c * 8 + k) * 3 + 0];
        s1 += g_scorep[(c * 8 + k) * 3 + 1];
        s2 += g_scorep[(c * 8 + k) * 3 + 2];
    }
    float bc = *bcomb;
    s0 += bc;
    s1 = g_hasmen[c] ? s1 + bc : -INFINITY;
    s2 = g_hasutt[c] ? s2 + bc : -INFINITY;
    float mx = fmaxf(s0, fmaxf(s1, s2));
    float e0 = expf(s0 - mx), e1 = expf(s1 - mx), e2 = expf(s2 - mx);
    float inv = 1.f / (e0 + e1 + e2);
    g_attn[c * 4 + 0] = e0 * inv;
    g_attn[c * 4 + 1] = e1 * inv;
    g_attn[c * 4 + 2] = e2 * inv;
}

// ---------------- K10: final combined token weights, transposed [T, Cpad] ----------------
__global__ void k_wt(const float* __restrict__ nmask, const float* __restrict__ umask) {
    __shared__ float sw[128 * CP];
    int t0 = blockIdx.x * 128;
    int t = t0 + threadIdx.x;
    float en = g_e_nts[t], em = g_e_mts[t], eu = g_e_uts[t];
    int b = t >> 9, s = t & (SS - 1);
#pragma unroll 1
    for (int c = 0; c < CC; c++) {
        float a0 = g_attn[c * 4 + 0], a1 = g_attn[c * 4 + 1], a2 = g_attn[c * 4 + 2];
        float wN = (nmask[c * SS + s] == 0.f) ? g_q[c * BB + b] * en : 0.f;
        float wM = g_gsum[(size_t)c * TT + t] * em;
        float wU = (umask[(size_t)c * TT + t] == 0.f) ? eu * g_invu[c] : 0.f;
        sw[threadIdx.x * CP + c] = a0 * wN + a1 * wM + a2 * wU;
    }
    sw[threadIdx.x * CP + 50] = 0.f;
    sw[threadIdx.x * CP + 51] = 0.f;
    __syncthreads();
    float* dst = g_WT + (size_t)t0 * CP;
    for (int i = threadIdx.x; i < 128 * CP; i += 128) dst[i] = sw[i];
}

// ---------------- K11: out = W[C,T] @ se[T,H], split-K with f32x2 FMAs ----------------
__global__ void __launch_bounds__(128) k_gemm(const float* __restrict__ se) {
    __shared__ __align__(16) float sw[64 * CP];
    int kc = blockIdx.x, ht = blockIdx.y;
    int h = ht * 128 + threadIdx.x;
    int t0 = kc * KCH;
    unsigned long long acc[25];
#pragma unroll
    for (int i = 0; i < 25; i++) acc[i] = 0ull;
    for (int tt = 0; tt < KCH; tt += 64) {
        __syncthreads();
        const float* src = g_WT + (size_t)(t0 + tt) * CP;
        for (int i = threadIdx.x; i < 64 * CP; i += 128) sw[i] = src[i];
        __syncthreads();
#pragma unroll 4
        for (int i = 0; i < 64; i++) {
            float sev = se[(size_t)(t0 + tt + i) * HH + h];
            unsigned long long sev2;
            asm("mov.b64 %0, {%1, %1};" : "=l"(sev2) : "f"(sev));
            const ulonglong2* wr = reinterpret_cast<const ulonglong2*>(&sw[i * CP]);
#pragma unroll
            for (int p = 0; p < 12; p++) {
                ulonglong2 w2 = wr[p];
                acc[2 * p]     = fma2(w2.x, sev2, acc[2 * p]);
                acc[2 * p + 1] = fma2(w2.y, sev2, acc[2 * p + 1]);
            }
            unsigned long long wlast =
                reinterpret_cast<const unsigned long long*>(&sw[i * CP])[24];
            acc[24] = fma2(wlast, sev2, acc[24]);
        }
    }
#pragma unroll
    for (int p = 0; p < 25; p++) {
        float2 v = *reinterpret_cast<float2*>(&acc[p]);
        g_partial[((size_t)kc * CC + 2 * p) * HH + h]     = v.x;
        g_partial[((size_t)kc * CC + 2 * p + 1) * HH + h] = v.y;
    }
}

// ---------------- K12: deterministic split-K reduction ----------------
__global__ void k_reduce(float* __restrict__ out) {
    int idx = blockIdx.x * 256 + threadIdx.x;
    if (idx >= CC * HH) return;
    float s0 = 0.f, s1 = 0.f, s2 = 0.f, s3 = 0.f;
#pragma unroll 4
    for (int k = 0; k < NK; k += 4) {
        s0 += g_partial[(size_t)(k + 0) * CC * HH + idx];
        s1 += g_partial[(size_t)(k + 1) * CC * HH + idx];
        s2 += g_partial[(size_t)(k + 2) * CC * HH + idx];
        s3 += g_partial[(size_t)(k + 3) * CC * HH + idx];
    }
    out[idx] = (s0 + s1) + (s2 + s3);
}

// ---------------- launch ----------------
extern "C" void kernel_launch(void* const* d_in, const int* in_sizes, int n_in,
                              void* d_out, int out_size) {
    const float* se    = (const float*)d_in[0];
    const float* nmask = (const float*)d_in[1];
    const float* umask = (const float*)d_in[2];
    const float* mmask = (const float*)d_in[3];
    const int*   seg   = (const int*)d_in[4];
    const float* wnt = (const float*)d_in[5];  const float* bnt = (const float*)d_in[6];
    const float* wn  = (const float*)d_in[7];  const float* bn  = (const float*)d_in[8];
    const float* wmt = (const float*)d_in[9];  const float* bmt = (const float*)d_in[10];
    const float* wm  = (const float*)d_in[11]; const float* bm  = (const float*)d_in[12];
    const float* wu  = (const float*)d_in[13]; const float* bu  = (const float*)d_in[14];
    const float* wc  = (const float*)d_in[15]; const float* bc  = (const float*)d_in[16];
    float* out = (float*)d_out;

    k_token<<<TT / 8, 256>>>(se, wnt, bnt, wn, bn, wmt, bmt, wm, bm, wu, bu, wc, bc);
    k_m1<<<MM, 256>>>(mmask, bm);
    k_seg<<<CC, 256>>>(seg);
    k_coef<<<(MM + 255) / 256, 256>>>(seg);
    k_gsum<<<dim3(CC, 8), 128>>>(seg);
    k_utt<<<CC, 256>>>(umask);
    k_names1<<<CC, 256>>>(nmask, bn);
    k_names2<<<CC, BB>>>();
    k_scores<<<dim3(CC, 8), 256>>>(nmask, umask);
    k_attn<<<1, 64>>>(bc);
    k_wt<<<TT / 128, 128>>>(nmask, umask);
    k_gemm<<<dim3(NK, HH / 128), 128>>>(se);
    k_reduce<<<(CC * HH + 255) / 256, 256>>>(out);
}

// round 2
// speedup vs baseline: 1.2011x; 1.2011x over previous
#include <cuda_runtime.h>
#include <math.h>

#define TT 32768
#define BB 64
#define SS 512
#define HH 768
#define CC 50
#define MM 2000
#define TW 1024          /* TT/32 */
#define NK 128           /* split-K chunks for final gemm */
#define KCH (TT/NK)      /* 256 tokens per chunk */
#define CP 52            /* C padded to multiple of 4 */
#define MLMAX 2048       /* max mentions per character (safe bound) */

// ---------------- scratch (static device memory; no allocations) ----------------
__device__ float g_e_nts[TT], g_vn[TT], g_e_mts[TT], g_vm[TT], g_e_uts[TT], g_vc[TT];
__device__ float g_den_m[MM], g_mscore[MM], g_coef[MM];
__device__ unsigned g_mbit[MM * TW];            // 8 MB mention-activity bitmask
__device__ int   g_mlist[CC * MLMAX];           // per-char mention index lists
__device__ int   g_mcnt[CC];
__device__ int   g_hasmen[CC];
__device__ float g_q[CC * BB];
__device__ float g_invu[CC];
__device__ int   g_hasutt[CC];
__device__ float g_gsum[(size_t)CC * TT];       // 6.5 MB per-char mention token coef sums
__device__ float g_scorep[CC * 8 * 3];
__device__ float g_WT[(size_t)TT * CP];         // transposed combined weights [T, Cpad]
__device__ float g_partial[(size_t)NK * CC * HH];

// ---------------- helpers ----------------
__device__ __forceinline__ float warpSum(float v) {
#pragma unroll
    for (int o = 16; o; o >>= 1) v += __shfl_down_sync(0xffffffffu, v, o);
    return v;
}
__device__ __forceinline__ float warpSumAll(float v) {
#pragma unroll
    for (int o = 16; o; o >>= 1) v += __shfl_xor_sync(0xffffffffu, v, o);
    return v;
}
__device__ __forceinline__ float warpMaxAll(float v) {
#pragma unroll
    for (int o = 16; o; o >>= 1) v = fmaxf(v, __shfl_xor_sync(0xffffffffu, v, o));
    return v;
}
// valid in thread 0 only
__device__ __forceinline__ float blockReduceSum(float v, float* sb) {
    __syncthreads();
    int lane = threadIdx.x & 31, w = threadIdx.x >> 5;
    v = warpSum(v);
    if (lane == 0) sb[w] = v;
    __syncthreads();
    float r = 0.f;
    if (w == 0) {
        int nw = blockDim.x >> 5;
        r = (lane < nw) ? sb[lane] : 0.f;
        r = warpSum(r);
    }
    return r;
}

__device__ __forceinline__ unsigned long long fma2(unsigned long long a,
                                                   unsigned long long b,
                                                   unsigned long long c) {
    unsigned long long d;
    asm("fma.rn.f32x2 %0, %1, %2, %3;" : "=l"(d) : "l"(a), "l"(b), "l"(c));
    return d;
}

// ---------------- K1: per-token scalar projections (one pass over story) ----------------
__global__ void k_token(const float* __restrict__ se, int t_off,
                        const float* __restrict__ wnt, const float* __restrict__ bnt,
                        const float* __restrict__ wn,  const float* __restrict__ bn,
                        const float* __restrict__ wmt, const float* __restrict__ bmt,
                        const float* __restrict__ wm,  const float* __restrict__ bm,
                        const float* __restrict__ wu,  const float* __restrict__ bu,
                        const float* __restrict__ wc,  const float* __restrict__ bc) {
    int gw = t_off + ((blockIdx.x * blockDim.x + threadIdx.x) >> 5);
    int lane = threadIdx.x & 31;
    if (gw >= TT) return;
    const float4* row = reinterpret_cast<const float4*>(se) + (size_t)gw * (HH / 4);
    const float4* W0 = reinterpret_cast<const float4*>(wnt);
    const float4* W1 = reinterpret_cast<const float4*>(wn);
    const float4* W2 = reinterpret_cast<const float4*>(wmt);
    const float4* W3 = reinterpret_cast<const float4*>(wm);
    const float4* W4 = reinterpret_cast<const float4*>(wu);
    const float4* W5 = reinterpret_cast<const float4*>(wc);
    float a0 = 0.f, a1 = 0.f, a2 = 0.f, a3 = 0.f, a4 = 0.f, a5 = 0.f;
#pragma unroll
    for (int i = 0; i < (HH / 4) / 32; i++) {
        int j = i * 32 + lane;
        float4 v = row[j];
        float4 w;
        w = W0[j]; a0 += v.x * w.x + v.y * w.y + v.z * w.z + v.w * w.w;
        w = W1[j]; a1 += v.x * w.x + v.y * w.y + v.z * w.z + v.w * w.w;
        w = W2[j]; a2 += v.x * w.x + v.y * w.y + v.z * w.z + v.w * w.w;
        w = W3[j]; a3 += v.x * w.x + v.y * w.y + v.z * w.z + v.w * w.w;
        w = W4[j]; a4 += v.x * w.x + v.y * w.y + v.z * w.z + v.w * w.w;
        w = W5[j]; a5 += v.x * w.x + v.y * w.y + v.z * w.z + v.w * w.w;
    }
    a0 = warpSum(a0); a1 = warpSum(a1); a2 = warpSum(a2);
    a3 = warpSum(a3); a4 = warpSum(a4); a5 = warpSum(a5);
    if (lane == 0) {
        g_e_nts[gw] = expf(a0 + *bnt);
        g_vn[gw]    = a1 + *bn;
        g_e_mts[gw] = expf(a2 + *bmt);
        g_vm[gw]    = a3 + *bm;
        g_e_uts[gw] = expf(a4 + *bu);
        g_vc[gw]    = a5 + *bc;
    }
}

// ---------------- K2: utterance denominators (half the chars per launch) ----------------
__global__ void k_utt(const float* __restrict__ umask, int c_off) {
    int c = c_off + blockIdx.x;
    const float4* row = reinterpret_cast<const float4*>(umask + (size_t)c * TT);
    float du = 0.f;
    for (int i = threadIdx.x; i < TT / 4; i += 256) {
        float4 v = row[i];
        int t = i * 4;
        if (v.x == 0.f) du += g_e_uts[t + 0];
        if (v.y == 0.f) du += g_e_uts[t + 1];
        if (v.z == 0.f) du += g_e_uts[t + 2];
        if (v.w == 0.f) du += g_e_uts[t + 3];
    }
    __shared__ float sb[8];
    float d = blockReduceSum(du, sb);
    if (threadIdx.x == 0) {
        g_hasutt[c] = (d > 0.f) ? 1 : 0;
        g_invu[c]   = (d > 0.f) ? 1.f / d : 0.f;
    }
}

// ---------------- K3: fused name rep: per-(c,b) den/score + block softmax -> q ----------------
__global__ void k_names(const float* __restrict__ nmask, const float* __restrict__ bname) {
    int c = blockIdx.x;
    __shared__ float smask[SS];
    __shared__ float sden[BB], snsc[BB];
    for (int i = threadIdx.x; i < SS; i += 256) smask[i] = nmask[c * SS + i];
    __syncthreads();
    int w = threadIdx.x >> 5, lane = threadIdx.x & 31;
    float bn_v = *bname;
    for (int b = w; b < BB; b += 8) {
        float den = 0.f, num = 0.f;
        for (int s = lane; s < SS; s += 32) {
            if (smask[s] == 0.f) {
                float e = g_e_nts[b * SS + s];
                den += e;
                num = fmaf(e, g_vn[b * SS + s], num);
            }
        }
        den = warpSumAll(den); num = warpSumAll(num);
        if (lane == 0) { sden[b] = den; snsc[b] = num / den + bn_v; }
    }
    __syncthreads();
    if (threadIdx.x < BB) {
        float v = snsc[threadIdx.x];
        float mx = -INFINITY;
#pragma unroll
        for (int i = 0; i < BB; i++) mx = fmaxf(mx, snsc[i]);
        float sum = 0.f;
#pragma unroll
        for (int i = 0; i < BB; i++) sum += expf(snsc[i] - mx);
        g_q[c * BB + threadIdx.x] = (expf(v - mx) / sum) / sden[threadIdx.x];
    }
}

// ---------------- K4: mention pass (single 262MB read; word-per-thread bitmask) ----------------
__global__ void k_m1(const float* __restrict__ mmask, const float* __restrict__ bmen) {
    int m = blockIdx.x;
    const float4* row = reinterpret_cast<const float4*>(mmask + (size_t)m * TT);
    float den = 0.f, num = 0.f;
#pragma unroll 1
    for (int wi = threadIdx.x; wi < TW; wi += 256) {   // 4 words per thread
        int t0 = wi * 32;
        unsigned bits = 0;
#pragma unroll
        for (int q8 = 0; q8 < 8; q8++) {
            float4 v = row[wi * 8 + q8];
            if (v.x == 0.f) bits |= 1u << (q8 * 4 + 0);
            if (v.y == 0.f) bits |= 1u << (q8 * 4 + 1);
            if (v.z == 0.f) bits |= 1u << (q8 * 4 + 2);
            if (v.w == 0.f) bits |= 1u << (q8 * 4 + 3);
        }
        g_mbit[(size_t)m * TW + wi] = bits;
        unsigned rem = bits;
        while (rem) {
            int b = __ffs(rem) - 1; rem &= rem - 1;
            int t = t0 + b;
            float e = g_e_mts[t];
            den += e;
            num = fmaf(e, g_vm[t], num);
        }
    }
    __shared__ float sb[8];
    float d = blockReduceSum(den, sb);
    float n = blockReduceSum(num, sb);
    if (threadIdx.x == 0) {
        g_den_m[m]  = d;
        g_mscore[m] = n / d + *bmen;
    }
}

// ---------------- K5: per-char mention lists + segment softmax + coefs (1 warp/char) ----------------
__global__ void k_seg2(const int* __restrict__ seg) {
    int c = blockIdx.x;
    int lane = threadIdx.x;
    int cnt = 0;
    float mx = -INFINITY;
    for (int base = 0; base < MM; base += 32) {
        int m = base + lane;
        bool match = (m < MM) && (seg[m] == c);
        unsigned bal = __ballot_sync(0xffffffffu, match);
        if (match) {
            int pos = cnt + __popc(bal & ((1u << lane) - 1u));
            g_mlist[c * MLMAX + pos] = m;
            mx = fmaxf(mx, g_mscore[m]);
        }
        cnt += __popc(bal);
    }
    mx = warpMaxAll(mx);
    float sum = 0.f;
    for (int i = lane; i < cnt; i += 32)
        sum += expf(g_mscore[g_mlist[c * MLMAX + i]] - mx);
    sum = warpSumAll(sum);
    for (int i = lane; i < cnt; i += 32) {
        int m = g_mlist[c * MLMAX + i];
        g_coef[m] = expf(g_mscore[m] - mx) / (sum * g_den_m[m]);
    }
    if (lane == 0) { g_mcnt[c] = cnt; g_hasmen[c] = (cnt > 0) ? 1 : 0; }
}

// ---------------- K6: gsum[c,t] = sum over c's mentions of coef_m * active(m,t) ----------------
__global__ void k_gsum() {
    __shared__ float st[128 * 33];
    int c = blockIdx.x;
    int wbase = blockIdx.y * 128 + threadIdx.x;   // word index in [0, TW)
    int cnt = g_mcnt[c];
    const int* list = g_mlist + c * MLMAX;
    float s[32];
#pragma unroll
    for (int b = 0; b < 32; b++) s[b] = 0.f;
    for (int i = 0; i < cnt; i++) {
        int m = list[i];
        unsigned w = g_mbit[(size_t)m * TW + wbase];
        if (w) {
            float cf = g_coef[m];
#pragma unroll
            for (int b = 0; b < 32; b++)
                if ((w >> b) & 1u) s[b] += cf;
        }
    }
#pragma unroll
    for (int b = 0; b < 32; b++) st[threadIdx.x * 33 + b] = s[b];
    __syncthreads();
    float* dst = g_gsum + (size_t)c * TT + (size_t)blockIdx.y * 4096;
    for (int j = threadIdx.x; j < 4096; j += 128)
        dst[j] = st[(j >> 5) * 33 + (j & 31)];
}

// ---------------- K7: combine scores s_k[c] = sum_t w_k[c,t] * vc[t] ----------------
__global__ void k_scores(const float* __restrict__ nmask, const float* __restrict__ umask) {
    int c = blockIdx.x, ch = blockIdx.y;
    int t0 = ch * (TT / 8);
    float invu = g_invu[c];
    float s0 = 0.f, s1 = 0.f, s2 = 0.f;
    for (int t = t0 + threadIdx.x; t < t0 + TT / 8; t += 256) {
        float vcv = g_vc[t];
        int b = t >> 9, s = t & (SS - 1);
        float wN = (nmask[c * SS + s] == 0.f) ? g_q[c * BB + b] * g_e_nts[t] : 0.f;
        float wM = g_gsum[(size_t)c * TT + t] * g_e_mts[t];
        float wU = (umask[(size_t)c * TT + t] == 0.f) ? g_e_uts[t] * invu : 0.f;
        s0 = fmaf(wN, vcv, s0);
        s1 = fmaf(wM, vcv, s1);
        s2 = fmaf(wU, vcv, s2);
    }
    __shared__ float sb[8];
    float r0 = blockReduceSum(s0, sb);
    float r1 = blockReduceSum(s1, sb);
    float r2 = blockReduceSum(s2, sb);
    if (threadIdx.x == 0) {
        g_scorep[(c * 8 + ch) * 3 + 0] = r0;
        g_scorep[(c * 8 + ch) * 3 + 1] = r1;
        g_scorep[(c * 8 + ch) * 3 + 2] = r2;
    }
}

// ---------------- K8: final combined token weights (attn softmax inline), [T, Cpad] ----------------
__global__ void k_wt(const float* __restrict__ nmask, const float* __restrict__ umask,
                     const float* __restrict__ bcomb) {
    __shared__ float sw[128 * CP];
    __shared__ float sattn[CC * 3];
    int t0 = blockIdx.x * 128;
    int t = t0 + threadIdx.x;
    if (threadIdx.x < CC) {
        int c = threadIdx.x;
        float s0 = 0.f, s1 = 0.f, s2 = 0.f;
#pragma unroll
        for (int k = 0; k < 8; k++) {
            s0 += g_scorep[(c * 8 + k) * 3 + 0];
            s1 += g_scorep[(c * 8 + k) * 3 + 1];
            s2 += g_scorep[(c * 8 + k) * 3 + 2];
        }
        float bc = *bcomb;
        s0 += bc;
        s1 = g_hasmen[c] ? s1 + bc : -INFINITY;
        s2 = g_hasutt[c] ? s2 + bc : -INFINITY;
        float mx = fmaxf(s0, fmaxf(s1, s2));
        float e0 = expf(s0 - mx), e1 = expf(s1 - mx), e2 = expf(s2 - mx);
        float inv = 1.f / (e0 + e1 + e2);
        sattn[c * 3 + 0] = e0 * inv;
        sattn[c * 3 + 1] = e1 * inv;
        sattn[c * 3 + 2] = e2 * inv;
    }
    __syncthreads();
    float en = g_e_nts[t], em = g_e_mts[t], eu = g_e_uts[t];
    int b = t >> 9, s = t & (SS - 1);
#pragma unroll 1
    for (int c = 0; c < CC; c++) {
        float a0 = sattn[c * 3 + 0], a1 = sattn[c * 3 + 1], a2 = sattn[c * 3 + 2];
        float wN = (nmask[c * SS + s] == 0.f) ? g_q[c * BB + b] * en : 0.f;
        float wM = g_gsum[(size_t)c * TT + t] * em;
        float wU = (umask[(size_t)c * TT + t] == 0.f) ? eu * g_invu[c] : 0.f;
        sw[threadIdx.x * CP + c] = a0 * wN + a1 * wM + a2 * wU;
    }
    sw[threadIdx.x * CP + 50] = 0.f;
    sw[threadIdx.x * CP + 51] = 0.f;
    __syncthreads();
    float* dst = g_WT + (size_t)t0 * CP;
    for (int i = threadIdx.x; i < 128 * CP; i += 128) dst[i] = sw[i];
}

// ---------------- K9: out = W[C,T] @ se[T,H], split-K with f32x2 FMAs ----------------
__global__ void __launch_bounds__(128) k_gemm(const float* __restrict__ se) {
    __shared__ __align__(16) float sw[64 * CP];
    int kc = blockIdx.x, ht = blockIdx.y;
    int h = ht * 128 + threadIdx.x;
    int t0 = kc * KCH;
    unsigned long long acc[25];
#pragma unroll
    for (int i = 0; i < 25; i++) acc[i] = 0ull;
    for (int tt = 0; tt < KCH; tt += 64) {
        __syncthreads();
        const float* src = g_WT + (size_t)(t0 + tt) * CP;
        for (int i = threadIdx.x; i < 64 * CP; i += 128) sw[i] = src[i];
        __syncthreads();
#pragma unroll 4
        for (int i = 0; i < 64; i++) {
            float sev = se[(size_t)(t0 + tt + i) * HH + h];
            unsigned long long sev2;
            asm("mov.b64 %0, {%1, %1};" : "=l"(sev2) : "f"(sev));
            const ulonglong2* wr = reinterpret_cast<const ulonglong2*>(&sw[i * CP]);
#pragma unroll
            for (int p = 0; p < 12; p++) {
                ulonglong2 w2 = wr[p];
                acc[2 * p]     = fma2(w2.x, sev2, acc[2 * p]);
                acc[2 * p + 1] = fma2(w2.y, sev2, acc[2 * p + 1]);
            }
            unsigned long long wlast =
                reinterpret_cast<const unsigned long long*>(&sw[i * CP])[24];
            acc[24] = fma2(wlast, sev2, acc[24]);
        }
    }
#pragma unroll
    for (int p = 0; p < 25; p++) {
        float2 v = *reinterpret_cast<float2*>(&acc[p]);
        g_partial[((size_t)kc * CC + 2 * p) * HH + h]     = v.x;
        g_partial[((size_t)kc * CC + 2 * p + 1) * HH + h] = v.y;
    }
}

// ---------------- K10: deterministic split-K reduction ----------------
__global__ void k_reduce(float* __restrict__ out) {
    int idx = blockIdx.x * 256 + threadIdx.x;
    if (idx >= CC * HH) return;
    float s0 = 0.f, s1 = 0.f, s2 = 0.f, s3 = 0.f;
#pragma unroll 4
    for (int k = 0; k < NK; k += 4) {
        s0 += g_partial[(size_t)(k + 0) * CC * HH + idx];
        s1 += g_partial[(size_t)(k + 1) * CC * HH + idx];
        s2 += g_partial[(size_t)(k + 2) * CC * HH + idx];
        s3 += g_partial[(size_t)(k + 3) * CC * HH + idx];
    }
    out[idx] = (s0 + s1) + (s2 + s3);
}

// ---------------- launch ----------------
extern "C" void kernel_launch(void* const* d_in, const int* in_sizes, int n_in,
                              void* d_out, int out_size) {
    const float* se    = (const float*)d_in[0];
    const float* nmask = (const float*)d_in[1];
    const float* umask = (const float*)d_in[2];
    const float* mmask = (const float*)d_in[3];
    const int*   seg   = (const int*)d_in[4];
    const float* wnt = (const float*)d_in[5];  const float* bnt = (const float*)d_in[6];
    const float* wn  = (const float*)d_in[7];  const float* bn  = (const float*)d_in[8];
    const float* wmt = (const float*)d_in[9];  const float* bmt = (const float*)d_in[10];
    const float* wm  = (const float*)d_in[11]; const float* bm  = (const float*)d_in[12];
    const float* wu  = (const float*)d_in[13]; const float* bu  = (const float*)d_in[14];
    const float* wc  = (const float*)d_in[15]; const float* bc  = (const float*)d_in[16];
    float* out = (float*)d_out;

    // order chosen so launch #6 (ncu -s 5 -c 1) is k_m1, the 262MB-read kernel
    k_token<<<TT / 16, 256>>>(se, 0,      wnt, bnt, wn, bn, wmt, bmt, wm, bm, wu, bu, wc, bc);
    k_token<<<TT / 16, 256>>>(se, TT / 2, wnt, bnt, wn, bn, wmt, bmt, wm, bm, wu, bu, wc, bc);
    k_utt<<<CC / 2, 256>>>(umask, 0);
    k_utt<<<CC / 2, 256>>>(umask, CC / 2);
    k_names<<<CC, 256>>>(nmask, bn);
    k_m1<<<MM, 256>>>(mmask, bm);
    k_seg2<<<CC, 32>>>(seg);
    k_gsum<<<dim3(CC, 8), 128>>>();
    k_scores<<<dim3(CC, 8), 256>>>(nmask, umask);
    k_wt<<<TT / 128, 128>>>(nmask, umask, bc);
    k_gemm<<<dim3(NK, HH / 128), 128>>>(se);
    k_reduce<<<(CC * HH + 255) / 256, 256>>>(out);
}